// round 2
// baseline (speedup 1.0000x reference)
#include <cuda_runtime.h>
#include <cstddef>

#define HIDDEN 1024
#define NHEAD  16
#define HD     64
#define BATCH  2
#define SEQ    2048
#define M_TOTAL (BATCH * SEQ)   // 4096
#define BH      (BATCH * NHEAD) // 32
#define QT      16              // query rows per attention CTA

// Scratch: Q/K/V in [b, h, s, d] layout (fp32)
__device__ float g_q[(size_t)BH * SEQ * HD];
__device__ float g_k[(size_t)BH * SEQ * HD];
__device__ float g_v[(size_t)BH * SEQ * HD];

// ---------------------------------------------------------------------------
// Fast exp: FMA-only (avoids MUFU bottleneck: 134M exps would cost ~900us on
// MUFU at 0.5/cyc/SM). Taylor deg-6 around 0 after range reduction to
// f in [-0.5, 0.5] in log2 domain. Rel err ~1e-7 for |x| < 10.
// ---------------------------------------------------------------------------
__device__ __forceinline__ float fexp(float x) {
    float t = x * 1.4426950408889634f;   // x * log2(e)
    float fi = rintf(t);
    float f = t - fi;
    float y = f * 0.6931471805599453f;   // back to ln domain, |y| <= 0.3466
    float p = 1.3888889e-3f;             // 1/720
    p = fmaf(p, y, 8.3333333e-3f);       // 1/120
    p = fmaf(p, y, 4.1666667e-2f);       // 1/24
    p = fmaf(p, y, 1.6666667e-1f);       // 1/6
    p = fmaf(p, y, 0.5f);
    p = fmaf(p, y, 1.0f);
    p = fmaf(p, y, 1.0f);
    int i = (int)fi;
    return p * __int_as_float((i + 127) << 23);
}

// ---------------------------------------------------------------------------
// K1: QKV projection.  C[m][n] = sum_k X[m][k] * W[n][k] + bias[n]
// Written to g_{q,k,v} in [b,h,s,d] layout.  64x64 tile, BK=32, 4x4 microtile.
// ---------------------------------------------------------------------------
__global__ __launch_bounds__(256) void qkv_kernel(
    const float* __restrict__ X,
    const float* __restrict__ Wq, const float* __restrict__ bq,
    const float* __restrict__ Wk, const float* __restrict__ bk,
    const float* __restrict__ Wv, const float* __restrict__ bv)
{
    __shared__ float As[32][68];  // As[k][m], pad 68 keeps float4 alignment (272B)
    __shared__ float Bs[32][68];  // Bs[k][n]

    const int which = blockIdx.z;
    const float* W    = (which == 0) ? Wq : (which == 1) ? Wk : Wv;
    const float* bias = (which == 0) ? bq : (which == 1) ? bk : bv;
    float* dst        = (which == 0) ? g_q : (which == 1) ? g_k : g_v;

    const int n0 = blockIdx.x * 64;
    const int m0 = blockIdx.y * 64;
    const int tid = threadIdx.x;
    const int ty = tid >> 4;      // 0..15
    const int tx = tid & 15;      // 0..15

    float acc[4][4];
    #pragma unroll
    for (int i = 0; i < 4; i++)
        #pragma unroll
        for (int j = 0; j < 4; j++) acc[i][j] = 0.0f;

    for (int k0 = 0; k0 < HIDDEN; k0 += 32) {
        #pragma unroll
        for (int it = 0; it < 2; it++) {
            int idx = tid + it * 256;          // 0..511 over 512 float4
            int r  = idx >> 3;                 // 0..63 tile row
            int c4 = (idx & 7) << 2;           // 0..28 k offset
            float4 xv = *(const float4*)&X[(size_t)(m0 + r) * HIDDEN + k0 + c4];
            As[c4 + 0][r] = xv.x; As[c4 + 1][r] = xv.y;
            As[c4 + 2][r] = xv.z; As[c4 + 3][r] = xv.w;
            float4 wv = *(const float4*)&W[(size_t)(n0 + r) * HIDDEN + k0 + c4];
            Bs[c4 + 0][r] = wv.x; Bs[c4 + 1][r] = wv.y;
            Bs[c4 + 2][r] = wv.z; Bs[c4 + 3][r] = wv.w;
        }
        __syncthreads();
        #pragma unroll
        for (int kk = 0; kk < 32; kk++) {
            float4 a = *(const float4*)&As[kk][ty << 2];
            float4 b = *(const float4*)&Bs[kk][tx << 2];
            float av[4] = {a.x, a.y, a.z, a.w};
            float bv4[4] = {b.x, b.y, b.z, b.w};
            #pragma unroll
            for (int i = 0; i < 4; i++)
                #pragma unroll
                for (int j = 0; j < 4; j++)
                    acc[i][j] = fmaf(av[i], bv4[j], acc[i][j]);
        }
        __syncthreads();
    }

    // Epilogue: add bias, scatter into [b,h,s,d] layout
    #pragma unroll
    for (int i = 0; i < 4; i++) {
        int m = m0 + (ty << 2) + i;
        int bb = m >> 11;           // m / 2048
        int s  = m & 2047;
        #pragma unroll
        for (int j = 0; j < 4; j++) {
            int n = n0 + (tx << 2) + j;
            int h = n >> 6;
            int d = n & 63;
            dst[(((size_t)bb * NHEAD + h) * SEQ + s) * HD + d] = acc[i][j] + bias[n];
        }
    }
}

// ---------------------------------------------------------------------------
// K2: attention.  One CTA = one (bh, 16-query-row tile).
// SMEM: es[16][2048] exp-scores (128KB) + kv tile [64][68] + q tile [16][68].
// Phase 1: scores + exp into es.  Phase 2: rowsum + normalize + probs store.
// Phase 3: P @ V -> ctx.
// ---------------------------------------------------------------------------
#define KV_PAD 68
#define ES_FLOATS   (QT * SEQ)            // 32768
#define KV_FLOATS   (64 * KV_PAD)         // 4352
#define QS_FLOATS   (QT * KV_PAD)         // 1088
#define ATTN_SMEM_BYTES ((ES_FLOATS + KV_FLOATS + QS_FLOATS) * 4)   // 152832

__global__ __launch_bounds__(256) void attn_kernel(float* __restrict__ out)
{
    extern __shared__ float sm[];
    float* es = sm;                        // [QT][SEQ]
    float* kv = sm + ES_FLOATS;            // [64][KV_PAD]
    float* qs = sm + ES_FLOATS + KV_FLOATS;// [QT][KV_PAD]
    __shared__ float rinv[QT];

    const int qb = blockIdx.x;             // 0..127
    const int bh = blockIdx.y;             // 0..31
    const int bb = bh >> 4;
    const int h  = bh & 15;
    const int tid = threadIdx.x;

    const float* Qp = g_q + ((size_t)bh * SEQ + (size_t)qb * QT) * HD;
    const float* Kp = g_k + (size_t)bh * SEQ * HD;
    const float* Vp = g_v + (size_t)bh * SEQ * HD;

    // Load Q tile [16][64]
    {
        int r = tid >> 4;
        int c = (tid & 15) << 2;
        *(float4*)&qs[r * KV_PAD + c] = *(const float4*)&Qp[r * HD + c];
    }

    const int qi = tid >> 4;        // 0..15  query row
    const int kc = (tid & 15) << 2; // 0..60  col group (4 cols / 4 d-values)

    // ---- Phase 1: scores -> exp -> es ----
    for (int k0 = 0; k0 < SEQ; k0 += 64) {
        #pragma unroll
        for (int it = 0; it < 4; it++) {
            int idx = tid + it * 256;
            int r = idx >> 4;
            int c = (idx & 15) << 2;
            *(float4*)&kv[r * KV_PAD + c] = *(const float4*)&Kp[(size_t)(k0 + r) * HD + c];
        }
        __syncthreads();

        float a0 = 0.f, a1 = 0.f, a2 = 0.f, a3 = 0.f;
        #pragma unroll
        for (int kk = 0; kk < HD; kk += 4) {
            float4 qv = *(const float4*)&qs[qi * KV_PAD + kk];
            float4 v0 = *(const float4*)&kv[(kc + 0) * KV_PAD + kk];
            float4 v1 = *(const float4*)&kv[(kc + 1) * KV_PAD + kk];
            float4 v2 = *(const float4*)&kv[(kc + 2) * KV_PAD + kk];
            float4 v3 = *(const float4*)&kv[(kc + 3) * KV_PAD + kk];
            a0 = fmaf(qv.x, v0.x, a0); a0 = fmaf(qv.y, v0.y, a0);
            a0 = fmaf(qv.z, v0.z, a0); a0 = fmaf(qv.w, v0.w, a0);
            a1 = fmaf(qv.x, v1.x, a1); a1 = fmaf(qv.y, v1.y, a1);
            a1 = fmaf(qv.z, v1.z, a1); a1 = fmaf(qv.w, v1.w, a1);
            a2 = fmaf(qv.x, v2.x, a2); a2 = fmaf(qv.y, v2.y, a2);
            a2 = fmaf(qv.z, v2.z, a2); a2 = fmaf(qv.w, v2.w, a2);
            a3 = fmaf(qv.x, v3.x, a3); a3 = fmaf(qv.y, v3.y, a3);
            a3 = fmaf(qv.z, v3.z, a3); a3 = fmaf(qv.w, v3.w, a3);
        }
        float4 e;
        e.x = fexp(a0 * 0.125f);
        e.y = fexp(a1 * 0.125f);
        e.z = fexp(a2 * 0.125f);
        e.w = fexp(a3 * 0.125f);
        *(float4*)&es[qi * SEQ + k0 + kc] = e;
        __syncthreads();
    }

    // ---- Phase 2: row sums (16 threads per row, shfl reduce within 16) ----
    {
        int row = tid >> 4;
        int l   = tid & 15;
        const float4* erow = (const float4*)&es[row * SEQ];
        float ps = 0.f;
        for (int j4 = l; j4 < SEQ / 4; j4 += 16) {
            float4 v = erow[j4];
            ps += (v.x + v.y) + (v.z + v.w);
        }
        #pragma unroll
        for (int o = 8; o > 0; o >>= 1)
            ps += __shfl_xor_sync(0xffffffffu, ps, o, 16);
        if (l == 0) rinv[row] = 1.0f / ps;
    }
    __syncthreads();

    // ---- Normalize in SMEM + write probs (fully coalesced; row block of
    //      probs for this CTA is contiguous: base + r*SEQ + j == base + idx) ----
    const size_t CTX_SIZE = (size_t)BATCH * SEQ * HIDDEN;   // 4,194,304
    float* probs = out + CTX_SIZE + ((size_t)bh * SEQ + (size_t)qb * QT) * SEQ;
    {
        float4* es4 = (float4*)es;
        float4* pr4 = (float4*)probs;
        for (int t4 = tid; t4 < (QT * SEQ) / 4; t4 += 256) {
            float ri = rinv[t4 >> 9];       // (t4*4) / 2048
            float4 v = es4[t4];
            v.x *= ri; v.y *= ri; v.z *= ri; v.w *= ri;
            es4[t4] = v;
            pr4[t4] = v;
        }
    }
    __syncthreads();

    // ---- Phase 3: ctx = P @ V ----
    float4 cacc = make_float4(0.f, 0.f, 0.f, 0.f);
    const int dc = kc;   // 4 head-dim cols owned by this thread
    for (int k0 = 0; k0 < SEQ; k0 += 64) {
        #pragma unroll
        for (int it = 0; it < 4; it++) {
            int idx = tid + it * 256;
            int r = idx >> 4;
            int c = (idx & 15) << 2;
            *(float4*)&kv[r * KV_PAD + c] = *(const float4*)&Vp[(size_t)(k0 + r) * HD + c];
        }
        __syncthreads();
        #pragma unroll 8
        for (int jj = 0; jj < 64; jj++) {
            float p = es[qi * SEQ + k0 + jj];
            float4 vv = *(const float4*)&kv[jj * KV_PAD + dc];
            cacc.x = fmaf(p, vv.x, cacc.x);
            cacc.y = fmaf(p, vv.y, cacc.y);
            cacc.z = fmaf(p, vv.z, cacc.z);
            cacc.w = fmaf(p, vv.w, cacc.w);
        }
        __syncthreads();
    }

    // ctx out layout [b][s][h*64+d]
    int srow = qb * QT + qi;
    float* ctx = out + ((size_t)bb * SEQ + srow) * HIDDEN + h * HD + dc;
    *(float4*)ctx = cacc;
}

// ---------------------------------------------------------------------------
extern "C" void kernel_launch(void* const* d_in, const int* in_sizes, int n_in,
                              void* d_out, int out_size)
{
    const float* X  = (const float*)d_in[0];
    const float* Wq = (const float*)d_in[1];
    const float* bq = (const float*)d_in[2];
    const float* Wk = (const float*)d_in[3];
    const float* bk = (const float*)d_in[4];
    const float* Wv = (const float*)d_in[5];
    const float* bv = (const float*)d_in[6];
    float* out = (float*)d_out;

    // K1: QKV projections (z selects Q/K/V)
    dim3 g1(HIDDEN / 64, M_TOTAL / 64, 3);
    qkv_kernel<<<g1, 256>>>(X, Wq, bq, Wk, bk, Wv, bv);

    // K2: attention (needs >48KB dynamic SMEM)
    cudaFuncSetAttribute(attn_kernel,
                         cudaFuncAttributeMaxDynamicSharedMemorySize,
                         ATTN_SMEM_BYTES);
    dim3 g2(SEQ / QT, BH);
    attn_kernel<<<g2, 256, ATTN_SMEM_BYTES>>>(out);
}

// round 5
// speedup vs baseline: 3.6726x; 3.6726x over previous
#include <cuda_runtime.h>
#include <cstddef>

#define HIDDEN 1024
#define NHEAD  16
#define HD     64
#define BATCH  2
#define SEQ    2048
#define M_TOTAL (BATCH * SEQ)   // 4096
#define BH      (BATCH * NHEAD) // 32
#define CTX_SIZE ((size_t)BATCH * SEQ * HIDDEN)  // 4,194,304

// Scratch: Q/K/V in [b,h,s,d] layout, plus exp-row-sums
__device__ float g_q[(size_t)BH * SEQ * HD];
__device__ float g_k[(size_t)BH * SEQ * HD];
__device__ float g_v[(size_t)BH * SEQ * HD];
__device__ float g_rsum[(size_t)BH * SEQ];

// ---------------------------------------------------------------------------
// FMA-only exp (MUFU would cost ~900us for 134M exps). Rel err ~1e-7.
// ---------------------------------------------------------------------------
__device__ __forceinline__ float fexp(float x) {
    float t = x * 1.4426950408889634f;
    float fi = rintf(t);
    float y = (t - fi) * 0.6931471805599453f;
    float p = 1.3888889e-3f;
    p = fmaf(p, y, 8.3333333e-3f);
    p = fmaf(p, y, 4.1666667e-2f);
    p = fmaf(p, y, 1.6666667e-1f);
    p = fmaf(p, y, 0.5f);
    p = fmaf(p, y, 1.0f);
    p = fmaf(p, y, 1.0f);
    return p * __int_as_float(((int)fi + 127) << 23);
}

// ---------------------------------------------------------------------------
// K0: zero the row-sum accumulator
// ---------------------------------------------------------------------------
__global__ void zero_rsum_kernel() {
    g_rsum[blockIdx.x * 256 + threadIdx.x] = 0.0f;
}

// ---------------------------------------------------------------------------
// K1: QKV projection.  C[m][n] = sum_k X[m][k]*W[n][k] + bias[n]
// 128x128 tile, BK=16, 8x8 microtile. Output scattered into [b,h,s,d].
// ---------------------------------------------------------------------------
__global__ __launch_bounds__(256) void qkv_kernel(
    const float* __restrict__ X,
    const float* __restrict__ Wq, const float* __restrict__ bq,
    const float* __restrict__ Wk, const float* __restrict__ bk,
    const float* __restrict__ Wv, const float* __restrict__ bv)
{
    __shared__ float As[16 * 132];   // [k][m], pitch 132
    __shared__ float Bs[16 * 132];   // [k][n]

    const int which = blockIdx.z;
    const float* W    = (which == 0) ? Wq : (which == 1) ? Wk : Wv;
    const float* bias = (which == 0) ? bq : (which == 1) ? bk : bv;
    float* dst        = (which == 0) ? g_q : (which == 1) ? g_k : g_v;

    const int n0 = blockIdx.x * 128;
    const int m0 = blockIdx.y * 128;
    const int tid = threadIdx.x;
    const int ty = tid >> 4;     // 0..15
    const int tx = tid & 15;     // 0..15

    float acc[8][8];
    #pragma unroll
    for (int i = 0; i < 8; i++)
        #pragma unroll
        for (int j = 0; j < 8; j++) acc[i][j] = 0.0f;

    for (int k0 = 0; k0 < HIDDEN; k0 += 16) {
        // stage X and W tiles transposed: 512 float4 each -> 2 per thread
        #pragma unroll
        for (int it = 0; it < 2; it++) {
            int f = tid + it * 256;
            int row = f >> 2;
            int c = (f & 3) << 2;
            float4 xv = *(const float4*)&X[(size_t)(m0 + row) * HIDDEN + k0 + c];
            As[(c + 0) * 132 + row] = xv.x; As[(c + 1) * 132 + row] = xv.y;
            As[(c + 2) * 132 + row] = xv.z; As[(c + 3) * 132 + row] = xv.w;
            float4 wv = *(const float4*)&W[(size_t)(n0 + row) * HIDDEN + k0 + c];
            Bs[(c + 0) * 132 + row] = wv.x; Bs[(c + 1) * 132 + row] = wv.y;
            Bs[(c + 2) * 132 + row] = wv.z; Bs[(c + 3) * 132 + row] = wv.w;
        }
        __syncthreads();
        #pragma unroll
        for (int kk = 0; kk < 16; kk++) {
            float4 a0 = *(const float4*)&As[kk * 132 + (ty << 2)];
            float4 a1 = *(const float4*)&As[kk * 132 + 64 + (ty << 2)];
            float4 b0 = *(const float4*)&Bs[kk * 132 + (tx << 2)];
            float4 b1 = *(const float4*)&Bs[kk * 132 + 64 + (tx << 2)];
            float a[8] = {a0.x, a0.y, a0.z, a0.w, a1.x, a1.y, a1.z, a1.w};
            float b[8] = {b0.x, b0.y, b0.z, b0.w, b1.x, b1.y, b1.z, b1.w};
            #pragma unroll
            for (int i = 0; i < 8; i++)
                #pragma unroll
                for (int j = 0; j < 8; j++)
                    acc[i][j] = fmaf(a[i], b[j], acc[i][j]);
        }
        __syncthreads();
    }

    // epilogue: bias + scatter to [b,h,s,d]
    float4 bv0 = *(const float4*)&bias[n0 + (tx << 2)];
    float4 bv1 = *(const float4*)&bias[n0 + 64 + (tx << 2)];
    float bb_[8] = {bv0.x, bv0.y, bv0.z, bv0.w, bv1.x, bv1.y, bv1.z, bv1.w};
    #pragma unroll
    for (int i = 0; i < 8; i++) {
        int m = m0 + ((i & 3) + (ty << 2)) + (i >> 2) * 64;
        int batch = m >> 11;
        int s = m & 2047;
        #pragma unroll
        for (int half = 0; half < 2; half++) {
            int n = n0 + half * 64 + (tx << 2);
            int h = n >> 6;
            int d = n & 63;
            float4 o;
            o.x = acc[i][half * 4 + 0] + bb_[half * 4 + 0];
            o.y = acc[i][half * 4 + 1] + bb_[half * 4 + 1];
            o.z = acc[i][half * 4 + 2] + bb_[half * 4 + 2];
            o.w = acc[i][half * 4 + 3] + bb_[half * 4 + 3];
            *(float4*)&dst[(((size_t)batch * NHEAD + h) * SEQ + s) * HD + d] = o;
        }
    }
}

// ---------------------------------------------------------------------------
// K2: scores.  E = exp(Q K^T / 8) written unnormalized into probs region.
// 64 q-rows x 128 keys per CTA, 4x8 microtile. Row-sum partials -> atomicAdd.
// ---------------------------------------------------------------------------
#define SC_SMEM ((64 * 68 + 64 * 132) * 4)   // 51200 bytes

__global__ __launch_bounds__(256) void scores_kernel(float* __restrict__ out)
{
    extern __shared__ float sm[];
    float* Qs = sm;             // [64 dims][68 rows]
    float* Ks = sm + 64 * 68;   // [64 dims][132 keys]

    const int kb = blockIdx.x;  // 0..15  key tile (128)
    const int qb = blockIdx.y;  // 0..31  q tile (64)
    const int bh = blockIdx.z;  // 0..31
    const int tid = threadIdx.x;

    const float* Qp = g_q + ((size_t)bh * SEQ + qb * 64) * HD;
    const float* Kp = g_k + ((size_t)bh * SEQ + kb * 128) * HD;

    #pragma unroll
    for (int it = 0; it < 4; it++) {          // Q: 1024 float4
        int f = tid + it * 256;
        int row = f >> 4;
        int c = (f & 15) << 2;
        float4 v = *(const float4*)&Qp[(size_t)row * HD + c];
        Qs[(c + 0) * 68 + row] = v.x; Qs[(c + 1) * 68 + row] = v.y;
        Qs[(c + 2) * 68 + row] = v.z; Qs[(c + 3) * 68 + row] = v.w;
    }
    #pragma unroll
    for (int it = 0; it < 8; it++) {          // K: 2048 float4
        int f = tid + it * 256;
        int key = f >> 4;
        int c = (f & 15) << 2;
        float4 v = *(const float4*)&Kp[(size_t)key * HD + c];
        Ks[(c + 0) * 132 + key] = v.x; Ks[(c + 1) * 132 + key] = v.y;
        Ks[(c + 2) * 132 + key] = v.z; Ks[(c + 3) * 132 + key] = v.w;
    }
    __syncthreads();

    const int ty = tid >> 4;
    const int tx = tid & 15;
    float acc[4][8];
    #pragma unroll
    for (int i = 0; i < 4; i++)
        #pragma unroll
        for (int j = 0; j < 8; j++) acc[i][j] = 0.0f;

    #pragma unroll 8
    for (int kk = 0; kk < 64; kk++) {
        float4 av = *(const float4*)&Qs[kk * 68 + (ty << 2)];
        float4 b0 = *(const float4*)&Ks[kk * 132 + (tx << 2)];
        float4 b1 = *(const float4*)&Ks[kk * 132 + 64 + (tx << 2)];
        float a[4] = {av.x, av.y, av.z, av.w};
        float b[8] = {b0.x, b0.y, b0.z, b0.w, b1.x, b1.y, b1.z, b1.w};
        #pragma unroll
        for (int i = 0; i < 4; i++)
            #pragma unroll
            for (int j = 0; j < 8; j++)
                acc[i][j] = fmaf(a[i], b[j], acc[i][j]);
    }

    float* Ebase = out + CTX_SIZE + ((size_t)bh * SEQ + qb * 64) * SEQ + kb * 128;
    #pragma unroll
    for (int i = 0; i < 4; i++) {
        float4 e0, e1;
        e0.x = fexp(acc[i][0] * 0.125f); e0.y = fexp(acc[i][1] * 0.125f);
        e0.z = fexp(acc[i][2] * 0.125f); e0.w = fexp(acc[i][3] * 0.125f);
        e1.x = fexp(acc[i][4] * 0.125f); e1.y = fexp(acc[i][5] * 0.125f);
        e1.z = fexp(acc[i][6] * 0.125f); e1.w = fexp(acc[i][7] * 0.125f);
        int row = (ty << 2) + i;
        *(float4*)&Ebase[(size_t)row * SEQ + (tx << 2)]      = e0;
        *(float4*)&Ebase[(size_t)row * SEQ + 64 + (tx << 2)] = e1;
        float rs = ((e0.x + e0.y) + (e0.z + e0.w)) + ((e1.x + e1.y) + (e1.z + e1.w));
        #pragma unroll
        for (int o = 8; o > 0; o >>= 1)
            rs += __shfl_xor_sync(0xffffffffu, rs, o, 16);
        if (tx == 0)
            atomicAdd(&g_rsum[(size_t)bh * SEQ + qb * 64 + row], rs);
    }
}

// ---------------------------------------------------------------------------
// K3: ctx = (E @ V) * rinv, and normalize probs in place.
// 128 q-rows x 64 d per CTA, keys streamed in tiles of 64. 8x4 microtile.
// E staged row-major with odd pitch 65 (conflict-free scalar load/store).
// ---------------------------------------------------------------------------
#define CT_SMEM ((128 * 65 + 64 * 68) * 4)   // 50688 bytes

__global__ __launch_bounds__(256) void ctx_kernel(float* __restrict__ out)
{
    extern __shared__ float sm[];
    float* Es = sm;                 // [128 rows][65]
    float* Vs = sm + 128 * 65;      // [64 keys][68 dims]
    __shared__ float rinv_s[128];

    const int qb = blockIdx.x;      // 0..15  (128-row tiles)
    const int bh = blockIdx.y;      // 0..31
    const int batch = bh >> 4;
    const int h = bh & 15;
    const int tid = threadIdx.x;

    if (tid < 128)
        rinv_s[tid] = 1.0f / g_rsum[(size_t)bh * SEQ + qb * 128 + tid];

    float* Erow = out + CTX_SIZE + ((size_t)bh * SEQ + qb * 128) * SEQ;
    const float* Vp = g_v + (size_t)bh * SEQ * HD;

    const int ty = tid >> 4;        // 0..15 -> rows ty*8..+7
    const int tx = tid & 15;        // 0..15 -> dims tx*4..+3
    float acc[8][4];
    #pragma unroll
    for (int i = 0; i < 8; i++)
        #pragma unroll
        for (int j = 0; j < 4; j++) acc[i][j] = 0.0f;

    for (int k0 = 0; k0 < SEQ; k0 += 64) {
        __syncthreads();   // protects smem reuse (and rinv_s on first iter)
        // V tile: 1024 float4
        #pragma unroll
        for (int it = 0; it < 4; it++) {
            int f = tid + it * 256;
            int key = f >> 4;
            int c = (f & 15) << 2;
            *(float4*)&Vs[key * 68 + c] =
                *(const float4*)&Vp[(size_t)(k0 + key) * HD + c];
        }
        // E tile: 2048 float4; normalize, write back probs, stage to smem
        #pragma unroll
        for (int it = 0; it < 8; it++) {
            int f = tid + it * 256;
            int row = f >> 4;
            int kc = (f & 15) << 2;
            float ri = rinv_s[row];
            float4 v = *(const float4*)&Erow[(size_t)row * SEQ + k0 + kc];
            v.x *= ri; v.y *= ri; v.z *= ri; v.w *= ri;
            *(float4*)&Erow[(size_t)row * SEQ + k0 + kc] = v;
            Es[row * 65 + kc + 0] = v.x; Es[row * 65 + kc + 1] = v.y;
            Es[row * 65 + kc + 2] = v.z; Es[row * 65 + kc + 3] = v.w;
        }
        __syncthreads();

        #pragma unroll 8
        for (int kk = 0; kk < 64; kk++) {
            float4 bv = *(const float4*)&Vs[kk * 68 + (tx << 2)];
            float a[8];
            #pragma unroll
            for (int i = 0; i < 8; i++)
                a[i] = Es[((ty << 3) + i) * 65 + kk];
            #pragma unroll
            for (int i = 0; i < 8; i++) {
                acc[i][0] = fmaf(a[i], bv.x, acc[i][0]);
                acc[i][1] = fmaf(a[i], bv.y, acc[i][1]);
                acc[i][2] = fmaf(a[i], bv.z, acc[i][2]);
                acc[i][3] = fmaf(a[i], bv.w, acc[i][3]);
            }
        }
    }

    // ctx out [b][s][h*64+d]
    #pragma unroll
    for (int i = 0; i < 8; i++) {
        int s = qb * 128 + (ty << 3) + i;
        float* p = out + ((size_t)batch * SEQ + s) * HIDDEN + h * HD + (tx << 2);
        *(float4*)p = make_float4(acc[i][0], acc[i][1], acc[i][2], acc[i][3]);
    }
}

// ---------------------------------------------------------------------------
extern "C" void kernel_launch(void* const* d_in, const int* in_sizes, int n_in,
                              void* d_out, int out_size)
{
    const float* X  = (const float*)d_in[0];
    const float* Wq = (const float*)d_in[1];
    const float* bq = (const float*)d_in[2];
    const float* Wk = (const float*)d_in[3];
    const float* bk = (const float*)d_in[4];
    const float* Wv = (const float*)d_in[5];
    const float* bv = (const float*)d_in[6];
    float* out = (float*)d_out;

    zero_rsum_kernel<<<BH * SEQ / 256, 256>>>();

    dim3 g1(HIDDEN / 128, M_TOTAL / 128, 3);
    qkv_kernel<<<g1, 256>>>(X, Wq, bq, Wk, bk, Wv, bv);

    cudaFuncSetAttribute(scores_kernel,
                         cudaFuncAttributeMaxDynamicSharedMemorySize, SC_SMEM);
    dim3 g2(SEQ / 128, SEQ / 64, BH);
    scores_kernel<<<g2, 256, SC_SMEM>>>(out);

    cudaFuncSetAttribute(ctx_kernel,
                         cudaFuncAttributeMaxDynamicSharedMemorySize, CT_SMEM);
    dim3 g3(SEQ / 128, BH);
    ctx_kernel<<<g3, 256, CT_SMEM>>>(out);
}